// round 6
// baseline (speedup 1.0000x reference)
#include <cuda_runtime.h>

// Output == input (reference returns x reshaped; everything else is dead code).
// Pure copy at the HBM3e r+w ceiling (~6.5 TB/s, 82% of spec).
// Persistent grid: 888 blocks (148 SMs x 6 resident) grid-stride over
// 8-batched float4 chunks -> no wave transitions, balanced tail.
// 128-bit accesses (256-bit measured slower in R5).

__global__ void __launch_bounds__(256) copy_persist(const float4* __restrict__ src,
                                                    float4* __restrict__ dst,
                                                    unsigned n4) {
    const unsigned stride = gridDim.x * 2048u;          // blocks * 256 threads * 8
    unsigned i = blockIdx.x * 2048u + threadIdx.x;
    // Full 8-batch iterations (no per-load guards).
    for (; i + 1792u < n4; i += stride) {
        float4 v0 = __ldcs(src + i);
        float4 v1 = __ldcs(src + i + 256u);
        float4 v2 = __ldcs(src + i + 512u);
        float4 v3 = __ldcs(src + i + 768u);
        float4 v4 = __ldcs(src + i + 1024u);
        float4 v5 = __ldcs(src + i + 1280u);
        float4 v6 = __ldcs(src + i + 1536u);
        float4 v7 = __ldcs(src + i + 1792u);
        __stcs(dst + i,          v0);
        __stcs(dst + i + 256u,   v1);
        __stcs(dst + i + 512u,   v2);
        __stcs(dst + i + 768u,   v3);
        __stcs(dst + i + 1024u,  v4);
        __stcs(dst + i + 1280u,  v5);
        __stcs(dst + i + 1536u,  v6);
        __stcs(dst + i + 1792u,  v7);
    }
    // Tail: remaining partial batch.
    for (; i < n4; i += 256u) {
        __stcs(dst + i, __ldcs(src + i));
    }
}

// Generic fallback for unexpected sizes / misalignment.
__global__ void copy_generic(const float* __restrict__ src, float* __restrict__ dst,
                             long long n) {
    long long i = (long long)blockIdx.x * blockDim.x + threadIdx.x;
    long long stride = (long long)gridDim.x * blockDim.x;
    for (; i < n; i += stride) dst[i] = src[i];
}

extern "C" void kernel_launch(void* const* d_in, const int* in_sizes, int n_in,
                              void* d_out, int out_size) {
    (void)n_in;
    long long n = out_size;
    long long nn = n;
    if ((long long)in_sizes[0] < nn) nn = in_sizes[0];
    if ((nn & 3LL) == 0 && nn == n) {
        unsigned n4 = (unsigned)(nn >> 2);              // 18,874,368 for this problem
        copy_persist<<<888, 256>>>((const float4*)d_in[0], (float4*)d_out, n4);
    } else {
        int blocks = (int)((nn + 255) / 256);
        if (blocks > 147456) blocks = 147456;
        copy_generic<<<blocks, 256>>>((const float*)d_in[0], (float*)d_out, nn);
    }
}

// round 7
// speedup vs baseline: 1.1013x; 1.1013x over previous
#include <cuda_runtime.h>

// Output == input (reference returns x reshaped; all other computation is dead).
// Pure copy at the HBM3e r+w-mix ceiling (~6.5 TB/s). One-shot exact-cover
// launch (monotone bid->address => sequential DRAM pages per SM).
// 16 front-batched 128-bit streaming loads per thread (MLP=16), then 16 stores.
// n float4 = 18,874,368 = 4608 blocks * 256 threads * 16 chunks exactly.

__global__ void __launch_bounds__(256) copy16_kernel(const float4* __restrict__ src,
                                                     float4* __restrict__ dst) {
    unsigned i = blockIdx.x * 4096u + threadIdx.x;  // 4096 = 256 * 16
    float4 v[16];
#pragma unroll
    for (int j = 0; j < 16; j++) v[j] = __ldcs(src + i + j * 256u);
#pragma unroll
    for (int j = 0; j < 16; j++) __stcs(dst + i + j * 256u, v[j]);
}

// Generic fallback for unexpected sizes / misalignment.
__global__ void copy_generic(const float* __restrict__ src, float* __restrict__ dst,
                             long long n) {
    long long i = (long long)blockIdx.x * blockDim.x + threadIdx.x;
    long long stride = (long long)gridDim.x * blockDim.x;
    for (; i < n; i += stride) dst[i] = src[i];
}

extern "C" void kernel_launch(void* const* d_in, const int* in_sizes, int n_in,
                              void* d_out, int out_size) {
    (void)n_in;
    long long n = out_size;
    if (n == 75497472LL && in_sizes[0] >= out_size) {
        copy16_kernel<<<4608, 256>>>((const float4*)d_in[0], (float4*)d_out);
    } else {
        long long nn = n;
        if ((long long)in_sizes[0] < nn) nn = in_sizes[0];
        int blocks = (int)((nn + 255) / 256);
        if (blocks > 147456) blocks = 147456;
        copy_generic<<<blocks, 256>>>((const float*)d_in[0], (float*)d_out, nn);
    }
}

// round 8
// speedup vs baseline: 1.1025x; 1.0010x over previous
#include <cuda_runtime.h>

// FINAL: Output == input (reference returns x.reshape(b,64,8,6,6).reshape(b,512,6,6)
// == x bit-exactly; 'features' and 'z' are deleted dead code). Pure 302 MB copy.
//
// Measured HBM3e r+w-mix ceiling on this GB300: ~6.50 TB/s (82% of 8 TB/s spec),
// hit identically by CE memcpy and kernels at MLP=4/8/16. This kernel is the
// best-measured variant: one-shot exact-cover launch (monotone bid->address for
// DRAM page locality), fully unrolled, guard-free, 8 front-batched 128-bit
// streaming loads per thread.
//
// n float4 = 18,874,368 = 9216 blocks * 256 threads * 8 chunks exactly.

__global__ void __launch_bounds__(256) copy8_kernel(const float4* __restrict__ src,
                                                    float4* __restrict__ dst) {
    unsigned i = blockIdx.x * 2048u + threadIdx.x;  // 2048 = 256 threads * 8 chunks
    float4 v0 = __ldcs(src + i);
    float4 v1 = __ldcs(src + i + 256u);
    float4 v2 = __ldcs(src + i + 512u);
    float4 v3 = __ldcs(src + i + 768u);
    float4 v4 = __ldcs(src + i + 1024u);
    float4 v5 = __ldcs(src + i + 1280u);
    float4 v6 = __ldcs(src + i + 1536u);
    float4 v7 = __ldcs(src + i + 1792u);
    __stcs(dst + i,          v0);
    __stcs(dst + i + 256u,   v1);
    __stcs(dst + i + 512u,   v2);
    __stcs(dst + i + 768u,   v3);
    __stcs(dst + i + 1024u,  v4);
    __stcs(dst + i + 1280u,  v5);
    __stcs(dst + i + 1536u,  v6);
    __stcs(dst + i + 1792u,  v7);
}

// Generic fallback for unexpected sizes.
__global__ void copy_generic(const float* __restrict__ src, float* __restrict__ dst,
                             long long n) {
    long long i = (long long)blockIdx.x * blockDim.x + threadIdx.x;
    long long stride = (long long)gridDim.x * blockDim.x;
    for (; i < n; i += stride) dst[i] = src[i];
}

extern "C" void kernel_launch(void* const* d_in, const int* in_sizes, int n_in,
                              void* d_out, int out_size) {
    (void)n_in;
    long long n = out_size;
    if (n == 75497472LL && in_sizes[0] >= out_size) {
        copy8_kernel<<<9216, 256>>>((const float4*)d_in[0], (float4*)d_out);
    } else {
        long long nn = n;
        if ((long long)in_sizes[0] < nn) nn = in_sizes[0];
        int blocks = (int)((nn + 255) / 256);
        if (blocks > 147456) blocks = 147456;
        copy_generic<<<blocks, 256>>>((const float*)d_in[0], (float*)d_out, nn);
    }
}

// round 9
// speedup vs baseline: 1.1134x; 1.0099x over previous
#include <cuda_runtime.h>

// FINAL FORM: Output == input (reference returns x reshaped bit-exactly; the
// attention machinery is deleted dead code). Pure 302 MB copy at the measured
// GB300 HBM3e r+w-mix ceiling (~6.55 TB/s, 82% of 8 TB/s spec), confirmed
// across CE memcpy and MLP=4/8/16 kernel shapes.
//
// One-shot exact-cover launch, monotone bid->address (DRAM page locality),
// fully unrolled/guard-free, 128-bit streaming accesses.
// n float4 = 18,874,368 = 9216 blocks * 512 threads * 4 chunks exactly.

__global__ void __launch_bounds__(512) copy8_kernel(const float4* __restrict__ src,
                                                    float4* __restrict__ dst) {
    unsigned i = blockIdx.x * 2048u + threadIdx.x;  // 2048 = 512 threads * 4 chunks
    float4 v0 = __ldcs(src + i);
    float4 v1 = __ldcs(src + i + 512u);
    float4 v2 = __ldcs(src + i + 1024u);
    float4 v3 = __ldcs(src + i + 1536u);
    __stcs(dst + i,          v0);
    __stcs(dst + i + 512u,   v1);
    __stcs(dst + i + 1024u,  v2);
    __stcs(dst + i + 1536u,  v3);
}

// Generic fallback for unexpected sizes.
__global__ void copy_generic(const float* __restrict__ src, float* __restrict__ dst,
                             long long n) {
    long long i = (long long)blockIdx.x * blockDim.x + threadIdx.x;
    long long stride = (long long)gridDim.x * blockDim.x;
    for (; i < n; i += stride) dst[i] = src[i];
}

extern "C" void kernel_launch(void* const* d_in, const int* in_sizes, int n_in,
                              void* d_out, int out_size) {
    (void)n_in;
    long long n = out_size;
    if (n == 75497472LL && in_sizes[0] >= out_size) {
        copy8_kernel<<<9216, 512>>>((const float4*)d_in[0], (float4*)d_out);
    } else {
        long long nn = n;
        if ((long long)in_sizes[0] < nn) nn = in_sizes[0];
        int blocks = (int)((nn + 255) / 256);
        if (blocks > 147456) blocks = 147456;
        copy_generic<<<blocks, 256>>>((const float*)d_in[0], (float*)d_out, nn);
    }
}